// round 8
// baseline (speedup 1.0000x reference)
#include <cuda_runtime.h>
#include <cstdint>
#include <math.h>

// Problem dims (fixed by the reference setup_inputs).
#define S_LEN 1024
#define B_N   64
#define I_DIM 1024
#define H_DIM 1024
#define M_TOT (S_LEN * B_N)   // 65536 = S*B

#define NCTA  128             // persistent grid (<= 148 SMs, 1 CTA/SM resident)
#define NTHR  256

// ---------------------------------------------------------------------------
// Scratch (device globals — no allocation allowed anywhere).
// ---------------------------------------------------------------------------
__device__ float g_x[(size_t)3 * M_TOT * H_DIM];   // xr/xz/xn  [3][S*B][H]
__device__ float g_h[2][B_N * H_DIM];              // hidden ping-pong
__device__ float g_rh[B_N * H_DIM];                // r (.) h
__device__ float g_z[B_N * H_DIM];                 // z gate

// grid-barrier state (zero-initialized; self-consistent across graph replays)
__device__ unsigned g_bar_count = 0;
__device__ unsigned g_bar_gen   = 0;

// ---------------------------------------------------------------------------
// tf32 helpers
// ---------------------------------------------------------------------------
__device__ __forceinline__ uint32_t f2tf(float f) {
    uint32_t u;
    asm("cvt.rna.tf32.f32 %0, %1;" : "=r"(u) : "f"(f));
    return u;
}

__device__ __forceinline__ void mma_tf32(float c[4],
        uint32_t a0, uint32_t a1, uint32_t a2, uint32_t a3,
        uint32_t b0, uint32_t b1) {
    asm volatile(
      "mma.sync.aligned.m16n8k8.row.col.f32.tf32.tf32.f32 "
      "{%0,%1,%2,%3}, {%4,%5,%6,%7}, {%8,%9}, {%0,%1,%2,%3};"
      : "+f"(c[0]), "+f"(c[1]), "+f"(c[2]), "+f"(c[3])
      : "r"(a0), "r"(a1), "r"(a2), "r"(a3), "r"(b0), "r"(b1));
}

// ---------------------------------------------------------------------------
// Software grid barrier (all NCTA CTAs resident by construction).
// Release: __threadfence before arrive; acquire: ld.acquire.gpu on the gen.
// ---------------------------------------------------------------------------
__device__ __forceinline__ unsigned ld_acq(unsigned* p) {
    unsigned v;
    asm volatile("ld.acquire.gpu.u32 %0, [%1];" : "=r"(v) : "l"(p) : "memory");
    return v;
}

__device__ __forceinline__ void grid_barrier() {
    __syncthreads();
    if (threadIdx.x == 0) {
        unsigned gen = ld_acq(&g_bar_gen);
        __threadfence();
        unsigned rank = atomicAdd(&g_bar_count, 1u);
        if (rank == NCTA - 1) {
            g_bar_count = 0;
            __threadfence();
            atomicAdd(&g_bar_gen, 1u);
        } else {
            while (ld_acq(&g_bar_gen) == gen) { __nanosleep(32); }
        }
    }
    __syncthreads();
}

// ---------------------------------------------------------------------------
// Shared-memory tile (shared by both phases). Stride 68 words:
// 68 mod 32 = 4  ->  fragment read addr mod 32 = 4g+tq = lane  (conflict-free).
// ---------------------------------------------------------------------------
struct SmemT {
    uint32_t A[64][68];   // A tile: 64 rows x 64 K (tf32)        17408 B
    uint32_t B[16][68];   // B tile: 16 out-cols x 64 K (tf32)     4352 B
};

// ---------------------------------------------------------------------------
// CTA GEMM: acc(64x16) += Am(64x1024, row-major) * Bm(16x1024, row-major)^T
// 8 warps = 4 row-strips (wm) x 2 col-halves (wn). K chunk 64, double-buffered
// via register prefetch. Dual accumulators break the MMA RAW chain.
// Result per lane (warp wm,wn): rows wm*16+g+{0,8}, cols wn*8+tq*2+{0,1}.
// ---------------------------------------------------------------------------
__device__ __forceinline__ void gemm_64x16(
    const float* Am, const float* Bm, SmemT* s, float accO[4])
{
    const int tid = threadIdx.x, lane = tid & 31, w = tid >> 5;
    const int wm = w & 3, wn = w >> 2, g = lane >> 2, tq = lane & 3;
    const int sar = tid >> 4;          // 0..15 (staging row)
    const int sac = (tid & 15) * 4;    // 0..60 (staging col, float4)
    const int r0  = wm * 16 + g;
    const int nb  = wn * 8 + g;

    float acc[2][4] = {};

    float4 pa[4], pb;
    #pragma unroll
    for (int u = 0; u < 4; ++u)
        pa[u] = *(const float4*)(Am + (size_t)(sar + 16 * u) * H_DIM + sac);
    pb = *(const float4*)(Bm + (size_t)sar * H_DIM + sac);

    for (int kc = 0; kc < H_DIM; kc += 64) {
        __syncthreads();   // previous chunk's MMA reads done
        #pragma unroll
        for (int u = 0; u < 4; ++u) {
            uint32_t* d = &s->A[sar + 16 * u][sac];
            d[0] = f2tf(pa[u].x); d[1] = f2tf(pa[u].y);
            d[2] = f2tf(pa[u].z); d[3] = f2tf(pa[u].w);
        }
        {
            uint32_t* d = &s->B[sar][sac];
            d[0] = f2tf(pb.x); d[1] = f2tf(pb.y);
            d[2] = f2tf(pb.z); d[3] = f2tf(pb.w);
        }
        __syncthreads();

        const int kn = kc + 64;
        if (kn < H_DIM) {  // prefetch next chunk while MMA runs
            #pragma unroll
            for (int u = 0; u < 4; ++u)
                pa[u] = *(const float4*)(Am + (size_t)(sar + 16 * u) * H_DIM + kn + sac);
            pb = *(const float4*)(Bm + (size_t)sar * H_DIM + kn + sac);
        }

        #pragma unroll
        for (int k8 = 0; k8 < 64; k8 += 8) {
            uint32_t a0 = s->A[r0    ][k8 + tq];
            uint32_t a1 = s->A[r0 + 8][k8 + tq];
            uint32_t a2 = s->A[r0    ][k8 + tq + 4];
            uint32_t a3 = s->A[r0 + 8][k8 + tq + 4];
            uint32_t b0 = s->B[nb][k8 + tq];
            uint32_t b1 = s->B[nb][k8 + tq + 4];
            mma_tf32(acc[(k8 >> 3) & 1], a0, a1, a2, a3, b0, b1);
        }
    }
    #pragma unroll
    for (int i = 0; i < 4; ++i) accO[i] = acc[0][i] + acc[1][i];
}

// ---------------------------------------------------------------------------
// Persistent recurrence kernel. 128 CTAs x 256 threads, 2 grid barriers/step.
// Phase 1: CTA c -> gate (c&1: 0=r, 1=z), cols (c>>1)*16 .. +15.
//          r-CTAs write rh = sigmoid(.)*h ; z-CTAs write z.
// Phase 2: CTAs 0..63 -> cols c*16 of n; gate update, write h' and out[t].
// ---------------------------------------------------------------------------
__global__ void __launch_bounds__(NTHR) k_recur(
    const float* __restrict__ whr, const float* __restrict__ whz,
    const float* __restrict__ whn,
    const float* __restrict__ bhr, const float* __restrict__ bhz,
    const float* __restrict__ bhn,
    float* out, int copy_hn)
{
    __shared__ SmemT s;
    const int c   = blockIdx.x;
    const int tid = threadIdx.x;
    const int lane = tid & 31, w = tid >> 5;
    const int wm = w & 3, wn = w >> 2, g = lane >> 2, tq = lane & 3;

    // h0 = 0  (each CTA zeroes its 512-float slice)
    #pragma unroll
    for (int u = 0; u < 2; ++u)
        g_h[0][c * 512 + u * 256 + tid] = 0.f;
    grid_barrier();

    const int   g01 = c & 1;                       // 0: r-gate, 1: z-gate
    const int   j1  = (c >> 1) * 16;
    const float* W1  = g01 ? whz : whr;
    const float* bh1 = g01 ? bhz : bhr;
    const int   j2  = c * 16;                      // phase-2 cols (c < 64)

    for (int t = 0; t < S_LEN; ++t) {
        const float* hin  = g_h[t & 1];
        float*       hout = g_h[(t + 1) & 1];

        // ---- phase 1: r, z ----
        {
            float acc[4];
            gemm_64x16(hin, W1 + (size_t)j1 * H_DIM, &s, acc);
            const float* xg = g_x + ((size_t)g01 * M_TOT + (size_t)t * B_N) * H_DIM;
            #pragma unroll
            for (int hh = 0; hh < 2; ++hh) {
                int b = wm * 16 + g + hh * 8;
                #pragma unroll
                for (int cc = 0; cc < 2; ++cc) {
                    int j = j1 + wn * 8 + tq * 2 + cc;
                    float v = acc[hh * 2 + cc] + xg[b * H_DIM + j] + bh1[j];
                    float sg = 1.f / (1.f + expf(-v));
                    if (g01 == 0) g_rh[b * H_DIM + j] = sg * hin[b * H_DIM + j];
                    else          g_z [b * H_DIM + j] = sg;
                }
            }
        }
        grid_barrier();

        // ---- phase 2: n + gate update ----
        if (c < 64) {
            float acc[4];
            gemm_64x16(g_rh, whn + (size_t)j2 * H_DIM, &s, acc);
            const float* xn = g_x + ((size_t)2 * M_TOT + (size_t)t * B_N) * H_DIM;
            #pragma unroll
            for (int hh = 0; hh < 2; ++hh) {
                int b = wm * 16 + g + hh * 8;
                #pragma unroll
                for (int cc = 0; cc < 2; ++cc) {
                    int j = j2 + wn * 8 + tq * 2 + cc;
                    float pre = acc[hh * 2 + cc] + xn[b * H_DIM + j] + bhn[j];
                    float nv  = tanhf(pre);
                    float zv  = g_z[b * H_DIM + j];
                    float hv  = (1.f - zv) * nv + zv * hin[b * H_DIM + j];
                    hout[b * H_DIM + j] = hv;
                    out[((size_t)t * B_N + b) * H_DIM + j] = hv;
                }
            }
        }
        grid_barrier();
    }

    if (copy_hn) {  // final h lives in g_h[0] after 1024 steps
        #pragma unroll
        for (int u = 0; u < 2; ++u) {
            int i = c * 512 + u * 256 + tid;
            out[(size_t)M_TOT * H_DIM + i] = g_h[0][i];
        }
    }
}

// ---------------------------------------------------------------------------
// Input projections: g_x[g][m][j] = input[m,:] . w_ih_g[j,:] + b_ih_g[j]
// CTA tile 128x128, 256 thr (2x4 warps, warp 64x32), K chunk 32.
// Grid (24, 512): x = gate*8 + jtile, y = mtile.
// ---------------------------------------------------------------------------
__global__ void __launch_bounds__(256) k_xproj(
    const float* __restrict__ input,
    const float* __restrict__ wr, const float* __restrict__ wz,
    const float* __restrict__ wn,
    const float* __restrict__ br, const float* __restrict__ bz,
    const float* __restrict__ bn)
{
    const int ntid  = blockIdx.x;            // 0..23
    const int mBase = blockIdx.y * 128;
    const int gate  = ntid >> 3;             // 0:r 1:z 2:n
    const int jBase = (ntid & 7) * 128;
    const float* W    = (gate == 0) ? wr : ((gate == 1) ? wz : wn);
    const float* bias = (gate == 0) ? br : ((gate == 1) ? bz : bn);

    __shared__ uint32_t As[128][36];
    __shared__ uint32_t Bs[128][36];

    const int tid  = threadIdx.x;
    const int lane = tid & 31;
    const int w    = tid >> 5;
    const int wm   = w & 1;
    const int wn_  = w >> 1;
    const int g    = lane >> 2;
    const int tq   = lane & 3;

    float acc[4][4][4];
    #pragma unroll
    for (int a = 0; a < 4; ++a)
        #pragma unroll
        for (int b = 0; b < 4; ++b)
            #pragma unroll
            for (int cc = 0; cc < 4; ++cc) acc[a][b][cc] = 0.f;

    for (int kc = 0; kc < I_DIM; kc += 32) {
        __syncthreads();
        #pragma unroll
        for (int i = tid; i < 1024; i += 256) {
            int r = i >> 3, c4 = (i & 7) * 4;
            float4 v = *(const float4*)(input + (size_t)(mBase + r) * I_DIM + kc + c4);
            As[r][c4+0] = f2tf(v.x); As[r][c4+1] = f2tf(v.y);
            As[r][c4+2] = f2tf(v.z); As[r][c4+3] = f2tf(v.w);
            float4 u = *(const float4*)(W + (size_t)(jBase + r) * I_DIM + kc + c4);
            Bs[r][c4+0] = f2tf(u.x); Bs[r][c4+1] = f2tf(u.y);
            Bs[r][c4+2] = f2tf(u.z); Bs[r][c4+3] = f2tf(u.w);
        }
        __syncthreads();

        #pragma unroll
        for (int k8 = 0; k8 < 32; k8 += 8) {
            uint32_t af[4][4];
            #pragma unroll
            for (int mt = 0; mt < 4; ++mt) {
                int rr = wm * 64 + mt * 16 + g;
                af[mt][0] = As[rr    ][k8 + tq];
                af[mt][1] = As[rr + 8][k8 + tq];
                af[mt][2] = As[rr    ][k8 + tq + 4];
                af[mt][3] = As[rr + 8][k8 + tq + 4];
            }
            #pragma unroll
            for (int nt = 0; nt < 4; ++nt) {
                int n0 = wn_ * 32 + nt * 8 + g;
                uint32_t b0 = Bs[n0][k8 + tq];
                uint32_t b1 = Bs[n0][k8 + tq + 4];
                #pragma unroll
                for (int mt = 0; mt < 4; ++mt)
                    mma_tf32(acc[mt][nt],
                             af[mt][0], af[mt][1], af[mt][2], af[mt][3], b0, b1);
            }
        }
    }

    #pragma unroll
    for (int mt = 0; mt < 4; ++mt) {
        #pragma unroll
        for (int nt = 0; nt < 4; ++nt) {
            int col = jBase + wn_ * 32 + nt * 8 + tq * 2;
            float b0 = __ldg(&bias[col]);
            float b1 = __ldg(&bias[col + 1]);
            #pragma unroll
            for (int hh = 0; hh < 2; ++hh) {
                int row = mBase + wm * 64 + mt * 16 + g + hh * 8;
                float2 v;
                v.x = acc[mt][nt][hh * 2 + 0] + b0;
                v.y = acc[mt][nt][hh * 2 + 1] + b1;
                *(float2*)(&g_x[((size_t)gate * M_TOT + row) * H_DIM + col]) = v;
            }
        }
    }
}

// ---------------------------------------------------------------------------
extern "C" void kernel_launch(void* const* d_in, const int* in_sizes, int n_in,
                              void* d_out, int out_size) {
    const float* input  = (const float*)d_in[0];
    const float* w_ih_r = (const float*)d_in[1];
    const float* w_hh_r = (const float*)d_in[2];
    const float* w_ih_z = (const float*)d_in[3];
    const float* w_hh_z = (const float*)d_in[4];
    const float* w_ih_n = (const float*)d_in[5];
    const float* w_hh_n = (const float*)d_in[6];
    const float* b_ih_r = (const float*)d_in[7];
    const float* b_hh_r = (const float*)d_in[8];
    const float* b_ih_z = (const float*)d_in[9];
    const float* b_hh_z = (const float*)d_in[10];
    const float* b_ih_n = (const float*)d_in[11];
    const float* b_hh_n = (const float*)d_in[12];
    float* out = (float*)d_out;

    const int copy_hn =
        (out_size >= (int)((size_t)M_TOT * H_DIM + (size_t)B_N * H_DIM)) ? 1 : 0;

    // 2 graph nodes total (keeps graph upload buffers tiny — no residual
    // device memory after teardown).
    k_xproj<<<dim3(24, 512), 256>>>(input, w_ih_r, w_ih_z, w_ih_n,
                                    b_ih_r, b_ih_z, b_ih_n);
    k_recur<<<NCTA, NTHR>>>(w_hh_r, w_hh_z, w_hh_n,
                            b_hh_r, b_hh_z, b_hh_n,
                            out, copy_hn);
}

// round 9
// speedup vs baseline: 1.3957x; 1.3957x over previous
#include <cuda_runtime.h>
#include <cstdint>
#include <math.h>

// Problem dims (fixed by the reference setup_inputs).
#define S_LEN 1024
#define B_N   64
#define I_DIM 1024
#define H_DIM 1024
#define M_TOT (S_LEN * B_N)   // 65536 = S*B

#define NCTA  128             // persistent grid, 1 CTA/SM (smem-bound), all resident
#define NTHR  256
#define NCH   16              // K chunks of 64

// ---------------------------------------------------------------------------
// Scratch (device globals — no allocation allowed anywhere).
// ---------------------------------------------------------------------------
__device__ float    g_x[(size_t)3 * M_TOT * H_DIM];  // xr/xz/xn  [3][S*B][H]
__device__ float    g_h[2][B_N * H_DIM];             // hidden (f32, for elementwise)
__device__ uint32_t g_h_tf[2][B_N * H_DIM];          // hidden pre-converted to tf32 (MMA A)
__device__ uint32_t g_rh_tf[B_N * H_DIM];            // (r .* h) in tf32 (MMA A, phase 2)

// grid-barrier state (zero-initialized; self-consistent across graph replays)
__device__ unsigned g_bar_count = 0;
__device__ unsigned g_bar_gen   = 0;

// ---------------------------------------------------------------------------
// tf32 helpers
// ---------------------------------------------------------------------------
__device__ __forceinline__ uint32_t f2tf(float f) {
    uint32_t u;
    asm("cvt.rna.tf32.f32 %0, %1;" : "=r"(u) : "f"(f));
    return u;
}

__device__ __forceinline__ void mma_tf32(float c[4],
        uint32_t a0, uint32_t a1, uint32_t a2, uint32_t a3,
        uint32_t b0, uint32_t b1) {
    asm volatile(
      "mma.sync.aligned.m16n8k8.row.col.f32.tf32.tf32.f32 "
      "{%0,%1,%2,%3}, {%4,%5,%6,%7}, {%8,%9}, {%0,%1,%2,%3};"
      : "+f"(c[0]), "+f"(c[1]), "+f"(c[2]), "+f"(c[3])
      : "r"(a0), "r"(a1), "r"(a2), "r"(a3), "r"(b0), "r"(b1));
}

// ---------------------------------------------------------------------------
// Software grid barrier (all NCTA CTAs resident by construction).
// ---------------------------------------------------------------------------
__device__ __forceinline__ unsigned ld_acq(unsigned* p) {
    unsigned v;
    asm volatile("ld.acquire.gpu.u32 %0, [%1];" : "=r"(v) : "l"(p) : "memory");
    return v;
}

__device__ __forceinline__ void grid_barrier() {
    __syncthreads();
    if (threadIdx.x == 0) {
        unsigned gen = ld_acq(&g_bar_gen);
        __threadfence();
        unsigned rank = atomicAdd(&g_bar_count, 1u);
        if (rank == NCTA - 1) {
            g_bar_count = 0;
            __threadfence();
            atomicAdd(&g_bar_gen, 1u);
        } else {
            while (ld_acq(&g_bar_gen) == gen) { __nanosleep(32); }
        }
    }
    __syncthreads();
}

// ---------------------------------------------------------------------------
// Dynamic shared memory.
// W strides 1028 (mod 32 == 4) and A stride 68 (mod 32 == 4) make the MMA
// fragment reads conflict-free: bank = 4g + tq + k8 (mod 32), all distinct.
// ---------------------------------------------------------------------------
struct SmemRec {
    uint32_t W1[16][1028];   // phase-1 weights: rows 0-7 = W_r cols, 8-15 = W_z cols
    uint32_t W2[8][1028];    // phase-2 weights: W_n cols
    uint32_t A[3][64][68];   // cp.async A-tile ring (3 stages x 64 rows x 64 K)
    float    z_s[64][8];     // z gate, CTA-local
    float    red[4][32][4];  // phase-2 K-split reduction
};
#define SMEM_RECUR ((int)sizeof(SmemRec))   // ~155 KB

// Issue one K-chunk of the A tile (64x64 tf32 words) via cp.async.cg.
// .cg bypasses L1 — mandatory: h/rh are written by other SMs each step and
// this SM's L1 can hold stale lines from earlier steps.
__device__ __forceinline__ void issue_chunk(SmemRec* s, const uint32_t* Atf,
                                            int ch, int arow, int aseg) {
    int st = ch % 3;
    const uint32_t* srcRow = Atf + (size_t)arow * H_DIM + ch * 64;
    uint32_t dbase = (uint32_t)__cvta_generic_to_shared(&s->A[st][arow][0]);
    #pragma unroll
    for (int i = 0; i < 4; ++i) {
        int cw = (aseg + 4 * i) * 4;           // word offset, 16B granularity
        asm volatile("cp.async.cg.shared.global [%0], [%1], 16;"
                     :: "r"(dbase + cw * 4), "l"(srcRow + cw));
    }
    asm volatile("cp.async.commit_group;" ::: "memory");
}

__device__ __forceinline__ void wait_stage(int ch) {
    if (ch < NCH - 1) asm volatile("cp.async.wait_group 1;" ::: "memory");
    else              asm volatile("cp.async.wait_group 0;" ::: "memory");
}

// ---------------------------------------------------------------------------
// Persistent recurrence kernel. 128 CTAs x 256 threads, 2 grid barriers/step.
// CTA c owns output columns j0 = c*8 .. j0+7 of ALL THREE gates.
//   Phase 1: 64x16 GEMM (cols 0-7 -> r, 8-15 -> z) from h_tf; writes rh_tf
//            (global) and z (smem).
//   Phase 2: 64x8 GEMM from rh_tf (K split over 2 warp groups); gate update
//            writes h' (f32 + tf32) and out[t].
// ---------------------------------------------------------------------------
__global__ void __launch_bounds__(NTHR) k_recur(
    const float* __restrict__ whr, const float* __restrict__ whz,
    const float* __restrict__ whn,
    const float* __restrict__ bhr, const float* __restrict__ bhz,
    const float* __restrict__ bhn,
    float* out, int copy_hn)
{
    extern __shared__ unsigned char smem_raw[];
    SmemRec* s = (SmemRec*)smem_raw;

    const int c    = blockIdx.x;
    const int tid  = threadIdx.x;
    const int lane = tid & 31, w = tid >> 5;
    const int wm   = w & 3;          // 16-row strip
    const int whi  = w >> 2;         // phase1: col half (r/z) ; phase2: K half
    const int g    = lane >> 2, tq = lane & 3;
    const int r0   = wm * 16 + g;
    const int arow = tid >> 2;       // cp.async staging row (0..63)
    const int aseg = tid & 3;        // staging 16B segment group
    const int j0   = c * 8;          // this CTA's column base (all gates)

    // ---- prologue: weights -> smem (tf32, swizzled), done once ----
    for (int idx = tid; idx < 16 * 256; idx += NTHR) {
        int row = idx >> 8;                 // 0..15
        int c4  = (idx & 255) * 4;          // 0..1020
        const float* src = (row < 8) ? (whr + (size_t)(j0 + row) * H_DIM)
                                     : (whz + (size_t)(j0 + row - 8) * H_DIM);
        float4 v = *(const float4*)(src + c4);
        uint32_t* d = &s->W1[row][c4];
        d[0] = f2tf(v.x); d[1] = f2tf(v.y); d[2] = f2tf(v.z); d[3] = f2tf(v.w);
    }
    for (int idx = tid; idx < 8 * 256; idx += NTHR) {
        int row = idx >> 8;
        int c4  = (idx & 255) * 4;
        float4 v = *(const float4*)(whn + (size_t)(j0 + row) * H_DIM + c4);
        uint32_t* d = &s->W2[row][c4];
        d[0] = f2tf(v.x); d[1] = f2tf(v.y); d[2] = f2tf(v.z); d[3] = f2tf(v.w);
    }
    // h0 = 0 (f32 and tf32 images)
    #pragma unroll
    for (int u = 0; u < 2; ++u) {
        int i = c * 512 + u * 256 + tid;
        g_h[0][i] = 0.f;
        g_h_tf[0][i] = 0u;
    }
    grid_barrier();

    for (int t = 0; t < S_LEN; ++t) {
        const float*    hin_f  = g_h[t & 1];
        const uint32_t* hin_tf = g_h_tf[t & 1];
        float*          hout_f  = g_h[(t + 1) & 1];
        uint32_t*       hout_tf = g_h_tf[(t + 1) & 1];

        // ================= phase 1: r, z =================
        {
            // epilogue operand prefetch (DRAM/L2 latency hidden behind GEMM)
            const float* xg1  = g_x + ((size_t)whi * M_TOT + (size_t)t * B_N) * H_DIM;
            const float* bias = whi ? bhz : bhr;
            float xpre[4], hpre[4], bpre[2];
            #pragma unroll
            for (int cc = 0; cc < 2; ++cc) bpre[cc] = bias[j0 + tq * 2 + cc];
            #pragma unroll
            for (int hh = 0; hh < 2; ++hh)
                #pragma unroll
                for (int cc = 0; cc < 2; ++cc) {
                    int b = wm * 16 + g + hh * 8;
                    int j = j0 + tq * 2 + cc;
                    xpre[hh * 2 + cc] = __ldcg(&xg1[(size_t)b * H_DIM + j]);
                    if (whi == 0) hpre[hh * 2 + cc] = __ldcg(&hin_f[b * H_DIM + j]);
                }

            float acc[2][4] = {};
            const int nb = whi * 8 + g;      // W1 row for B fragment

            issue_chunk(s, hin_tf, 0, arow, aseg);
            issue_chunk(s, hin_tf, 1, arow, aseg);
            for (int ch = 0; ch < NCH; ++ch) {
                wait_stage(ch);
                __syncthreads();
                if (ch + 2 < NCH) issue_chunk(s, hin_tf, ch + 2, arow, aseg);
                const int st = ch % 3, kb = ch * 64;
                #pragma unroll
                for (int k8 = 0; k8 < 64; k8 += 8) {
                    uint32_t a0 = s->A[st][r0    ][k8 + tq];
                    uint32_t a1 = s->A[st][r0 + 8][k8 + tq];
                    uint32_t a2 = s->A[st][r0    ][k8 + tq + 4];
                    uint32_t a3 = s->A[st][r0 + 8][k8 + tq + 4];
                    uint32_t b0 = s->W1[nb][kb + k8 + tq];
                    uint32_t b1 = s->W1[nb][kb + k8 + tq + 4];
                    mma_tf32(acc[(k8 >> 3) & 1], a0, a1, a2, a3, b0, b1);
                }
            }

            #pragma unroll
            for (int hh = 0; hh < 2; ++hh)
                #pragma unroll
                for (int cc = 0; cc < 2; ++cc) {
                    int i = hh * 2 + cc;
                    int b = wm * 16 + g + hh * 8;
                    int j = j0 + tq * 2 + cc;
                    float v  = acc[0][i] + acc[1][i] + xpre[i] + bpre[cc];
                    float sg = 1.f / (1.f + expf(-v));
                    if (whi == 0)
                        g_rh_tf[b * H_DIM + j] = f2tf(sg * hpre[i]);
                    else
                        s->z_s[b][tq * 2 + cc] = sg;
                }
        }
        grid_barrier();

        // ================= phase 2: n + gate update =================
        {
            const float* xn = g_x + ((size_t)2 * M_TOT + (size_t)t * B_N) * H_DIM;
            float xpre[4], hpre[4], bpre[2];
            if (whi == 0) {      // only wk==0 warps do the epilogue
                #pragma unroll
                for (int cc = 0; cc < 2; ++cc) bpre[cc] = bhn[j0 + tq * 2 + cc];
                #pragma unroll
                for (int hh = 0; hh < 2; ++hh)
                    #pragma unroll
                    for (int cc = 0; cc < 2; ++cc) {
                        int b = wm * 16 + g + hh * 8;
                        int j = j0 + tq * 2 + cc;
                        xpre[hh * 2 + cc] = __ldcg(&xn[(size_t)b * H_DIM + j]);
                        hpre[hh * 2 + cc] = __ldcg(&hin_f[b * H_DIM + j]);
                    }
            }

            float acc[2][4] = {};
            issue_chunk(s, g_rh_tf, 0, arow, aseg);
            issue_chunk(s, g_rh_tf, 1, arow, aseg);
            for (int ch = 0; ch < NCH; ++ch) {
                wait_stage(ch);
                __syncthreads();
                if (ch + 2 < NCH) issue_chunk(s, g_rh_tf, ch + 2, arow, aseg);
                const int st = ch % 3, kb = ch * 64;
                #pragma unroll
                for (int m = 0; m < 4; ++m) {      // this warp's K quarter-steps
                    int k8 = whi * 32 + m * 8;
                    uint32_t a0 = s->A[st][r0    ][k8 + tq];
                    uint32_t a1 = s->A[st][r0 + 8][k8 + tq];
                    uint32_t a2 = s->A[st][r0    ][k8 + tq + 4];
                    uint32_t a3 = s->A[st][r0 + 8][k8 + tq + 4];
                    uint32_t b0 = s->W2[g][kb + k8 + tq];
                    uint32_t b1 = s->W2[g][kb + k8 + tq + 4];
                    mma_tf32(acc[m & 1], a0, a1, a2, a3, b0, b1);
                }
            }

            if (whi == 1) {      // K-half reduction through smem
                #pragma unroll
                for (int i = 0; i < 4; ++i)
                    s->red[wm][lane][i] = acc[0][i] + acc[1][i];
            }
            __syncthreads();
            if (whi == 0) {
                #pragma unroll
                for (int hh = 0; hh < 2; ++hh)
                    #pragma unroll
                    for (int cc = 0; cc < 2; ++cc) {
                        int i = hh * 2 + cc;
                        int b = wm * 16 + g + hh * 8;
                        int j = j0 + tq * 2 + cc;
                        float pre = acc[0][i] + acc[1][i] + s->red[wm][lane][i]
                                  + xpre[i] + bpre[cc];
                        float nv = tanhf(pre);
                        float zv = s->z_s[b][tq * 2 + cc];
                        float hv = (1.f - zv) * nv + zv * hpre[i];
                        hout_f[b * H_DIM + j]  = hv;
                        hout_tf[b * H_DIM + j] = f2tf(hv);
                        out[((size_t)t * B_N + b) * H_DIM + j] = hv;
                    }
            }
        }
        grid_barrier();
    }

    if (copy_hn) {  // final h lives in g_h[0] after 1024 steps
        #pragma unroll
        for (int u = 0; u < 2; ++u) {
            int i = c * 512 + u * 256 + tid;
            out[(size_t)M_TOT * H_DIM + i] = __ldcg(&g_h[0][i]);
        }
    }
}

// ---------------------------------------------------------------------------
// Input projections: g_x[g][m][j] = input[m,:] . w_ih_g[j,:] + b_ih_g[j]
// (unchanged from the passing round-8 kernel; ~2.7 ms)
// ---------------------------------------------------------------------------
__global__ void __launch_bounds__(256) k_xproj(
    const float* __restrict__ input,
    const float* __restrict__ wr, const float* __restrict__ wz,
    const float* __restrict__ wn,
    const float* __restrict__ br, const float* __restrict__ bz,
    const float* __restrict__ bn)
{
    const int ntid  = blockIdx.x;            // 0..23
    const int mBase = blockIdx.y * 128;
    const int gate  = ntid >> 3;             // 0:r 1:z 2:n
    const int jBase = (ntid & 7) * 128;
    const float* W    = (gate == 0) ? wr : ((gate == 1) ? wz : wn);
    const float* bias = (gate == 0) ? br : ((gate == 1) ? bz : bn);

    __shared__ uint32_t As[128][36];
    __shared__ uint32_t Bs[128][36];

    const int tid  = threadIdx.x;
    const int lane = tid & 31;
    const int w    = tid >> 5;
    const int wm   = w & 1;
    const int wn_  = w >> 1;
    const int g    = lane >> 2;
    const int tq   = lane & 3;

    float acc[4][4][4];
    #pragma unroll
    for (int a = 0; a < 4; ++a)
        #pragma unroll
        for (int b = 0; b < 4; ++b)
            #pragma unroll
            for (int cc = 0; cc < 4; ++cc) acc[a][b][cc] = 0.f;

    for (int kc = 0; kc < I_DIM; kc += 32) {
        __syncthreads();
        #pragma unroll
        for (int i = tid; i < 1024; i += 256) {
            int r = i >> 3, c4 = (i & 7) * 4;
            float4 v = *(const float4*)(input + (size_t)(mBase + r) * I_DIM + kc + c4);
            As[r][c4+0] = f2tf(v.x); As[r][c4+1] = f2tf(v.y);
            As[r][c4+2] = f2tf(v.z); As[r][c4+3] = f2tf(v.w);
            float4 u = *(const float4*)(W + (size_t)(jBase + r) * I_DIM + kc + c4);
            Bs[r][c4+0] = f2tf(u.x); Bs[r][c4+1] = f2tf(u.y);
            Bs[r][c4+2] = f2tf(u.z); Bs[r][c4+3] = f2tf(u.w);
        }
        __syncthreads();

        #pragma unroll
        for (int k8 = 0; k8 < 32; k8 += 8) {
            uint32_t af[4][4];
            #pragma unroll
            for (int mt = 0; mt < 4; ++mt) {
                int rr = wm * 64 + mt * 16 + g;
                af[mt][0] = As[rr    ][k8 + tq];
                af[mt][1] = As[rr + 8][k8 + tq];
                af[mt][2] = As[rr    ][k8 + tq + 4];
                af[mt][3] = As[rr + 8][k8 + tq + 4];
            }
            #pragma unroll
            for (int nt = 0; nt < 4; ++nt) {
                int n0 = wn_ * 32 + nt * 8 + g;
                uint32_t b0 = Bs[n0][k8 + tq];
                uint32_t b1 = Bs[n0][k8 + tq + 4];
                #pragma unroll
                for (int mt = 0; mt < 4; ++mt)
                    mma_tf32(acc[mt][nt],
                             af[mt][0], af[mt][1], af[mt][2], af[mt][3], b0, b1);
            }
        }
    }

    #pragma unroll
    for (int mt = 0; mt < 4; ++mt) {
        #pragma unroll
        for (int nt = 0; nt < 4; ++nt) {
            int col = jBase + wn_ * 32 + nt * 8 + tq * 2;
            float b0 = __ldg(&bias[col]);
            float b1 = __ldg(&bias[col + 1]);
            #pragma unroll
            for (int hh = 0; hh < 2; ++hh) {
                int row = mBase + wm * 64 + mt * 16 + g + hh * 8;
                float2 v;
                v.x = acc[mt][nt][hh * 2 + 0] + b0;
                v.y = acc[mt][nt][hh * 2 + 1] + b1;
                *(float2*)(&g_x[((size_t)gate * M_TOT + row) * H_DIM + col]) = v;
            }
        }
    }
}

// ---------------------------------------------------------------------------
extern "C" void kernel_launch(void* const* d_in, const int* in_sizes, int n_in,
                              void* d_out, int out_size) {
    const float* input  = (const float*)d_in[0];
    const float* w_ih_r = (const float*)d_in[1];
    const float* w_hh_r = (const float*)d_in[2];
    const float* w_ih_z = (const float*)d_in[3];
    const float* w_hh_z = (const float*)d_in[4];
    const float* w_ih_n = (const float*)d_in[5];
    const float* w_hh_n = (const float*)d_in[6];
    const float* b_ih_r = (const float*)d_in[7];
    const float* b_hh_r = (const float*)d_in[8];
    const float* b_ih_z = (const float*)d_in[9];
    const float* b_hh_z = (const float*)d_in[10];
    const float* b_ih_n = (const float*)d_in[11];
    const float* b_hh_n = (const float*)d_in[12];
    float* out = (float*)d_out;

    const int copy_hn =
        (out_size >= (int)((size_t)M_TOT * H_DIM + (size_t)B_N * H_DIM)) ? 1 : 0;

    cudaFuncSetAttribute(k_recur, cudaFuncAttributeMaxDynamicSharedMemorySize,
                         SMEM_RECUR);

    // 2 graph nodes total.
    k_xproj<<<dim3(24, 512), 256>>>(input, w_ih_r, w_ih_z, w_ih_n,
                                    b_ih_r, b_ih_z, b_ih_n);
    k_recur<<<NCTA, NTHR, SMEM_RECUR>>>(w_hh_r, w_hh_z, w_hh_n,
                                        b_hh_r, b_hh_z, b_hh_n,
                                        out, copy_hn);
}